// round 2
// baseline (speedup 1.0000x reference)
#include <cuda_runtime.h>
#include <cstdint>

// CutOut: out = images with a 50x50 window (centered per-batch) zeroed.
// images: (B=64, H=512, W=512, C=3) fp32, row-major.  Row = W*C = 1536 floats
// = 384 float4s.  One 384-thread block per (b, h) row; grid = B*H = 32768.
// Labels (64 x int32) are appended CONVERTED TO FLOAT (harness output buffer
// is a single float32 array holding both outputs concatenated).

#define Bsz  64
#define Hsz  512
#define Wsz  512
#define Csz  3
#define HALF 25
#define ROW_FLOATS   (Wsz * Csz)       // 1536
#define ROW_VEC4     (ROW_FLOATS / 4)  // 384
#define IMG_FLOATS   (Hsz * ROW_FLOATS)
#define TOTAL_FLOATS (Bsz * IMG_FLOATS)

__global__ __launch_bounds__(ROW_VEC4)
void cutout_kernel(const float4* __restrict__ in,
                   float4* __restrict__ out,
                   const int* __restrict__ center_h,
                   const int* __restrict__ center_w)
{
    const int row_id = blockIdx.x;          // 0 .. B*H-1
    const int b = row_id >> 9;              // / 512
    const int h = row_id & (Hsz - 1);       // % 512

    const long base = (long)row_id * ROW_VEC4;
    const int t = threadIdx.x;

    float4 v = in[base + t];

    const int ch = __ldg(&center_h[b]);
    if (h >= ch - HALF && h < ch + HALF) {
        const int cw = __ldg(&center_w[b]);
        const int w_lo = cw - HALF;
        const int w_hi = cw + HALF;
        const int e0 = t * 4;               // element index within row
        // element e -> w = e / 3
        int w;
        w = e0 / 3;        if (w >= w_lo && w < w_hi) v.x = 0.0f;
        w = (e0 + 1) / 3;  if (w >= w_lo && w < w_hi) v.y = 0.0f;
        w = (e0 + 2) / 3;  if (w >= w_lo && w < w_hi) v.z = 0.0f;
        w = (e0 + 3) / 3;  if (w >= w_lo && w < w_hi) v.w = 0.0f;
    }

    out[base + t] = v;
}

__global__ void labels_kernel(const int* __restrict__ labels,
                              float* __restrict__ out_tail)
{
    int t = threadIdx.x;
    if (t < Bsz) out_tail[t] = (float)labels[t];
}

extern "C" void kernel_launch(void* const* d_in, const int* in_sizes, int n_in,
                              void* d_out, int out_size)
{
    const float* images   = (const float*)d_in[0];
    const int*   labels   = (const int*)d_in[1];
    const int*   center_h = (const int*)d_in[2];
    const int*   center_w = (const int*)d_in[3];

    float* out = (float*)d_out;

    cutout_kernel<<<Bsz * Hsz, ROW_VEC4>>>(
        (const float4*)images, (float4*)out, center_h, center_w);

    labels_kernel<<<1, 64>>>(labels, out + TOTAL_FLOATS);
}

// round 3
// speedup vs baseline: 1.0272x; 1.0272x over previous
#include <cuda_runtime.h>
#include <cstdint>

// CutOut: out = images with a 50x50 window (centered per-batch) zeroed.
// images: (B=64, H=512, W=512, C=3) fp32, row-major.  Row = W*C = 1536 floats
// = 384 float4s.  One 384-thread block per (b, h) row; grid = B*H = 32768.
// Labels (64 x int32 -> float) are written by block 0 (fused; the separate
// 64-thread kernel cost 3.7us of launch overhead).

#define Bsz  64
#define Hsz  512
#define Wsz  512
#define Csz  3
#define HALF 25
#define ROW_FLOATS   (Wsz * Csz)       // 1536
#define ROW_VEC4     (ROW_FLOATS / 4)  // 384
#define IMG_FLOATS   (Hsz * ROW_FLOATS)
#define TOTAL_FLOATS (Bsz * IMG_FLOATS)

__global__ __launch_bounds__(ROW_VEC4)
void cutout_kernel(const float4* __restrict__ in,
                   float4* __restrict__ out,
                   const int* __restrict__ labels,
                   const int* __restrict__ center_h,
                   const int* __restrict__ center_w)
{
    const int row_id = blockIdx.x;          // 0 .. B*H-1
    const int b = row_id >> 9;              // / 512
    const int h = row_id & (Hsz - 1);       // % 512

    const long base = (long)row_id * ROW_VEC4;
    const int t = threadIdx.x;

    float4 v = in[base + t];

    const int ch = __ldg(&center_h[b]);
    if (h >= ch - HALF && h < ch + HALF) {
        const int cw = __ldg(&center_w[b]);
        const int w_lo = cw - HALF;
        const int w_hi = cw + HALF;
        const int e0 = t * 4;               // element index within row
        // element e -> w = e / 3
        int w;
        w = e0 / 3;        if (w >= w_lo && w < w_hi) v.x = 0.0f;
        w = (e0 + 1) / 3;  if (w >= w_lo && w < w_hi) v.y = 0.0f;
        w = (e0 + 2) / 3;  if (w >= w_lo && w < w_hi) v.z = 0.0f;
        w = (e0 + 3) / 3;  if (w >= w_lo && w < w_hi) v.w = 0.0f;
    }

    out[base + t] = v;

    // Fused labels pass-through (int32 -> float32), done once by block 0.
    if (row_id == 0 && t < Bsz) {
        float* tail = (float*)out + TOTAL_FLOATS;
        tail[t] = (float)__ldg(&labels[t]);
    }
}

extern "C" void kernel_launch(void* const* d_in, const int* in_sizes, int n_in,
                              void* d_out, int out_size)
{
    const float* images   = (const float*)d_in[0];
    const int*   labels   = (const int*)d_in[1];
    const int*   center_h = (const int*)d_in[2];
    const int*   center_w = (const int*)d_in[3];

    float* out = (float*)d_out;

    cutout_kernel<<<Bsz * Hsz, ROW_VEC4>>>(
        (const float4*)images, (float4*)out, labels, center_h, center_w);
}

// round 4
// speedup vs baseline: 1.0565x; 1.0285x over previous
#include <cuda_runtime.h>
#include <cstdint>

// CutOut: out = images with a 50x50 window (centered per-batch) zeroed.
// images: (B=64, H=512, W=512, C=3) fp32.  Row = 1536 floats = 384 float4s.
// One 384-thread block handles 4 consecutive rows of one image (MLP=4,
// front-batched loads) -> grid = B*H/4 = 8192.  Streaming hints (ldcs/stcs):
// data is touched exactly once.  Labels fused into block 0.

#define Bsz  64
#define Hsz  512
#define Wsz  512
#define Csz  3
#define HALF 25
#define ROW_FLOATS   (Wsz * Csz)       // 1536
#define ROW_VEC4     (ROW_FLOATS / 4)  // 384
#define TOTAL_FLOATS (Bsz * Hsz * ROW_FLOATS)
#define ROWS_PER_BLK 4

__global__ __launch_bounds__(ROW_VEC4)
void cutout_kernel(const float4* __restrict__ in,
                   float4* __restrict__ out,
                   const int* __restrict__ labels,
                   const int* __restrict__ center_h,
                   const int* __restrict__ center_w)
{
    const int row0 = blockIdx.x * ROWS_PER_BLK;   // first global row
    const int b  = row0 >> 9;                     // / 512 (4 rows same image)
    const int h0 = row0 & (Hsz - 1);              // % 512

    const int t = threadIdx.x;
    const long base = (long)row0 * ROW_VEC4 + t;

    // Front-batched loads: 4 outstanding float4 loads per thread.
    float4 v0 = __ldcs(&in[base]);
    float4 v1 = __ldcs(&in[base +     ROW_VEC4]);
    float4 v2 = __ldcs(&in[base + 2 * ROW_VEC4]);
    float4 v3 = __ldcs(&in[base + 3 * ROW_VEC4]);

    const int ch = __ldg(&center_h[b]);
    const int h_lo = ch - HALF, h_hi = ch + HALF;

    // Does any of our 4 rows intersect the vertical band?
    if (h0 + ROWS_PER_BLK > h_lo && h0 < h_hi) {
        const int cw = __ldg(&center_w[b]);
        const int w_lo = cw - HALF, w_hi = cw + HALF;
        const int e0 = t * 4;
        int w;
        w = e0 / 3;        const bool mx = (w >= w_lo) && (w < w_hi);
        w = (e0 + 1) / 3;  const bool my = (w >= w_lo) && (w < w_hi);
        w = (e0 + 2) / 3;  const bool mz = (w >= w_lo) && (w < w_hi);
        w = (e0 + 3) / 3;  const bool mw = (w >= w_lo) && (w < w_hi);

        if (h0     >= h_lo && h0     < h_hi) {
            if (mx) v0.x = 0.f; if (my) v0.y = 0.f;
            if (mz) v0.z = 0.f; if (mw) v0.w = 0.f;
        }
        if (h0 + 1 >= h_lo && h0 + 1 < h_hi) {
            if (mx) v1.x = 0.f; if (my) v1.y = 0.f;
            if (mz) v1.z = 0.f; if (mw) v1.w = 0.f;
        }
        if (h0 + 2 >= h_lo && h0 + 2 < h_hi) {
            if (mx) v2.x = 0.f; if (my) v2.y = 0.f;
            if (mz) v2.z = 0.f; if (mw) v2.w = 0.f;
        }
        if (h0 + 3 >= h_lo && h0 + 3 < h_hi) {
            if (mx) v3.x = 0.f; if (my) v3.y = 0.f;
            if (mz) v3.z = 0.f; if (mw) v3.w = 0.f;
        }
    }

    __stcs(&out[base],                v0);
    __stcs(&out[base +     ROW_VEC4], v1);
    __stcs(&out[base + 2 * ROW_VEC4], v2);
    __stcs(&out[base + 3 * ROW_VEC4], v3);

    // Fused labels pass-through (int32 -> float32), once, by block 0.
    if (blockIdx.x == 0 && t < Bsz) {
        float* tail = (float*)out + TOTAL_FLOATS;
        tail[t] = (float)__ldg(&labels[t]);
    }
}

extern "C" void kernel_launch(void* const* d_in, const int* in_sizes, int n_in,
                              void* d_out, int out_size)
{
    const float* images   = (const float*)d_in[0];
    const int*   labels   = (const int*)d_in[1];
    const int*   center_h = (const int*)d_in[2];
    const int*   center_w = (const int*)d_in[3];

    float* out = (float*)d_out;

    cutout_kernel<<<(Bsz * Hsz) / ROWS_PER_BLK, ROW_VEC4>>>(
        (const float4*)images, (float4*)out, labels, center_h, center_w);
}